// round 1
// baseline (speedup 1.0000x reference)
#include <cuda_runtime.h>
#include <math.h>
#include <stdint.h>

#define N_TOK 16384
#define D_DIM 1024
#define N_EXP 64
#define CAPACITY 640
#define CHUNK 256
#define NCHUNK (N_TOK / CHUNK)   // 64

// ---------------- scratch (static device globals; no runtime alloc) ----------
__device__ int   g_topidx[N_TOK * 2];       // [N][2] expert ids (top-k order)
__device__ float g_gates [N_TOK * 2];       // [N][2] softmax gates
__device__ int   g_hist  [2 * NCHUNK * N_EXP];
__device__ int   g_basep [2 * NCHUNK * N_EXP];
__device__ int   g_cnt   [N_EXP];           // min(total, CAPACITY)
__device__ int   g_slot  [N_TOK * 2];       // raw dispatch slot per (n,k)
__device__ int   g_toklist[N_EXP * CAPACITY]; // entry = token*2 + k
__device__ float g_ybuf[(size_t)N_TOK * 2 * D_DIM]; // per (n,k) expert output

// ---------------- router: logits GEMM + top2 + softmax, warp per token -------
__device__ __forceinline__ bool beats(float v, int i, float v2, int i2) {
    return (v > v2) || (v == v2 && i < i2);
}

__global__ __launch_bounds__(256) void router_kernel(
    const float* __restrict__ x, const float* __restrict__ Wr,
    const float* __restrict__ br)
{
    __shared__ float WrS[64 * 64];   // Wr chunk: rows d0..d0+63 x 64 experts
    __shared__ float xS[8 * 64];     // per-warp token slice
    int tid  = threadIdx.x;
    int warp = tid >> 5, lane = tid & 31;
    int token = blockIdx.x * 8 + warp;
    const float* xrow = x + (size_t)token * D_DIM;

    int ea = 2 * lane, eb = 2 * lane + 1;
    float acc0 = br[ea], acc1 = br[eb];

    for (int d0 = 0; d0 < D_DIM; d0 += 64) {
        __syncthreads();
        // load Wr chunk (64x64 floats) with float4
        for (int i = tid; i < 64 * 16; i += 256) {
            int r = i >> 4, c4 = (i & 15) * 4;
            *(float4*)(WrS + r * 64 + c4) =
                *(const float4*)(Wr + (size_t)(d0 + r) * N_EXP + c4);
        }
        xS[warp * 64 + lane]      = xrow[d0 + lane];
        xS[warp * 64 + lane + 32] = xrow[d0 + lane + 32];
        __syncthreads();
        #pragma unroll
        for (int d = 0; d < 64; ++d) {
            float xv = xS[warp * 64 + d];
            float2 w = *(const float2*)(WrS + d * 64 + ea);
            acc0 = fmaf(xv, w.x, acc0);
            acc1 = fmaf(xv, w.y, acc1);
        }
    }

    // local sorted pair
    float v1, v2; int i1, i2;
    if (beats(acc1, eb, acc0, ea)) { v1 = acc1; i1 = eb; v2 = acc0; i2 = ea; }
    else                           { v1 = acc0; i1 = ea; v2 = acc1; i2 = eb; }

    // butterfly merge of sorted pairs -> warp-wide top2 (ties: lower index)
    #pragma unroll
    for (int off = 16; off >= 1; off >>= 1) {
        float ov1 = __shfl_xor_sync(0xffffffffu, v1, off);
        int   oi1 = __shfl_xor_sync(0xffffffffu, i1, off);
        float ov2 = __shfl_xor_sync(0xffffffffu, v2, off);
        int   oi2 = __shfl_xor_sync(0xffffffffu, i2, off);
        if (beats(ov1, oi1, v1, i1)) {
            if (beats(ov2, oi2, v1, i1)) { v2 = ov2; i2 = oi2; }
            else                         { v2 = v1;  i2 = i1;  }
            v1 = ov1; i1 = oi1;
        } else {
            if (beats(ov1, oi1, v2, i2)) { v2 = ov1; i2 = oi1; }
        }
    }

    if (lane == 0) {
        float e1 = expf(v2 - v1);            // v1 is max
        float inv = 1.0f / (1.0f + e1);
        g_topidx[2 * token]     = i1;
        g_topidx[2 * token + 1] = i2;
        g_gates [2 * token]     = inv;
        g_gates [2 * token + 1] = e1 * inv;
    }
}

// ---------------- histogram per (k, chunk) -----------------------------------
__global__ __launch_bounds__(256) void hist_kernel()
{
    int k = blockIdx.x >> 6, chunk = blockIdx.x & 63;
    __shared__ int cnt[N_EXP];
    int tid = threadIdx.x;
    if (tid < N_EXP) cnt[tid] = 0;
    __syncthreads();
    int token = chunk * CHUNK + tid;
    int e = g_topidx[token * 2 + k];
    atomicAdd(&cnt[e], 1);
    __syncthreads();
    if (tid < N_EXP) g_hist[(k * NCHUNK + chunk) * N_EXP + tid] = cnt[tid];
}

// ---------------- exclusive scan over k-major chunks, per expert -------------
__global__ void scan_kernel()
{
    int e = threadIdx.x;   // 64 threads
    int run = 0;
    for (int i = 0; i < 2 * NCHUNK; ++i) {
        g_basep[i * N_EXP + e] = run;
        run += g_hist[i * N_EXP + e];
    }
    g_cnt[e] = run < CAPACITY ? run : CAPACITY;
}

// ---------------- assign slots in order, build token lists -------------------
__global__ __launch_bounds__(32) void assign_kernel()
{
    int k = blockIdx.x >> 6, chunk = blockIdx.x & 63;
    int lane = threadIdx.x;
    __shared__ int run[N_EXP];
    run[lane] = 0; run[lane + 32] = 0;
    __syncwarp();
    int baseoff = (k * NCHUNK + chunk) * N_EXP;
    #pragma unroll
    for (int g = 0; g < CHUNK / 32; ++g) {
        int token = chunk * CHUNK + g * 32 + lane;
        int e = g_topidx[token * 2 + k];
        unsigned m = __match_any_sync(0xffffffffu, e);
        int leader = __ffs(m) - 1;
        int rank = __popc(m & ((1u << lane) - 1u));
        int old = 0;
        if (lane == leader) old = atomicAdd(&run[e], __popc(m));
        old = __shfl_sync(0xffffffffu, old, leader);
        int slot = g_basep[baseoff + e] + old + rank;
        g_slot[token * 2 + k] = slot;
        if (slot < CAPACITY) g_toklist[e * CAPACITY + slot] = token * 2 + k;
    }
}

// ---------------- grouped expert GEMM: y = relu(gather(x) @ We[e]) -----------
// tile 128x128x8, 256 threads, 8x8 per thread, fp32
__global__ __launch_bounds__(256, 2) void expert_gemm(
    const float* __restrict__ x, const float* __restrict__ We)
{
    int e = blockIdx.z;
    int cnt = g_cnt[e];
    int m0 = blockIdx.y * 128;
    if (m0 >= cnt) return;
    int n0 = blockIdx.x * 128;

    __shared__ float As[8][128];
    __shared__ float Bs[8][128];
    __shared__ int rowent[128];

    int tid = threadIdx.x;
    if (tid < 128) {
        int r = m0 + tid;
        rowent[tid] = (r < cnt) ? g_toklist[e * CAPACITY + r] : -1;
    }
    __syncthreads();

    int arow = tid >> 1;
    int akq  = (tid & 1) * 4;
    int ent  = rowent[arow];
    const float* xrow = x + (size_t)(ent >= 0 ? (ent >> 1) : 0) * D_DIM;

    int bk = tid >> 5;
    int bn = (tid & 31) * 4;
    const float* B = We + (size_t)e * D_DIM * D_DIM;

    int tx = tid & 15, ty = tid >> 4;
    float c[8][8] = {};

    for (int k0 = 0; k0 < D_DIM; k0 += 8) {
        float4 av = *(const float4*)(xrow + k0 + akq);
        float4 bv = *(const float4*)(B + (size_t)(k0 + bk) * D_DIM + n0 + bn);
        As[akq + 0][arow] = av.x;
        As[akq + 1][arow] = av.y;
        As[akq + 2][arow] = av.z;
        As[akq + 3][arow] = av.w;
        *(float4*)&Bs[bk][bn] = bv;
        __syncthreads();
        #pragma unroll
        for (int kk = 0; kk < 8; ++kk) {
            float4 a0 = *(const float4*)&As[kk][ty * 8];
            float4 a1 = *(const float4*)&As[kk][ty * 8 + 4];
            float4 b0 = *(const float4*)&Bs[kk][tx * 8];
            float4 b1 = *(const float4*)&Bs[kk][tx * 8 + 4];
            float a[8] = {a0.x, a0.y, a0.z, a0.w, a1.x, a1.y, a1.z, a1.w};
            float b[8] = {b0.x, b0.y, b0.z, b0.w, b1.x, b1.y, b1.z, b1.w};
            #pragma unroll
            for (int i = 0; i < 8; ++i)
                #pragma unroll
                for (int j = 0; j < 8; ++j)
                    c[i][j] = fmaf(a[i], b[j], c[i][j]);
        }
        __syncthreads();
    }

    #pragma unroll
    for (int i = 0; i < 8; ++i) {
        int m = ty * 8 + i;
        if (m0 + m < cnt) {
            int eid = rowent[m];
            float* yrow = g_ybuf + (size_t)eid * D_DIM + n0 + tx * 8;
            float4 o0, o1;
            o0.x = fmaxf(c[i][0], 0.f); o0.y = fmaxf(c[i][1], 0.f);
            o0.z = fmaxf(c[i][2], 0.f); o0.w = fmaxf(c[i][3], 0.f);
            o1.x = fmaxf(c[i][4], 0.f); o1.y = fmaxf(c[i][5], 0.f);
            o1.z = fmaxf(c[i][6], 0.f); o1.w = fmaxf(c[i][7], 0.f);
            *(float4*)(yrow)     = o0;
            *(float4*)(yrow + 4) = o1;
        }
    }
}

// ---------------- combine: out[n] = g0*y(n,0) + g1*y(n,1) --------------------
__global__ __launch_bounds__(256) void combine_kernel(float* __restrict__ out)
{
    int t = blockIdx.x;
    int d = threadIdx.x * 4;
    int s0 = g_slot[2 * t], s1 = g_slot[2 * t + 1];
    float g0 = g_gates[2 * t], g1 = g_gates[2 * t + 1];
    float4 acc = make_float4(0.f, 0.f, 0.f, 0.f);
    if (s0 < CAPACITY) {
        float4 v = *(const float4*)(g_ybuf + (size_t)(2 * t) * D_DIM + d);
        acc.x += g0 * v.x; acc.y += g0 * v.y; acc.z += g0 * v.z; acc.w += g0 * v.w;
    }
    if (s1 < CAPACITY) {
        float4 v = *(const float4*)(g_ybuf + (size_t)(2 * t + 1) * D_DIM + d);
        acc.x += g1 * v.x; acc.y += g1 * v.y; acc.z += g1 * v.z; acc.w += g1 * v.w;
    }
    *(float4*)(out + (size_t)t * D_DIM + d) = acc;
}

// ---------------- launch ------------------------------------------------------
extern "C" void kernel_launch(void* const* d_in, const int* in_sizes, int n_in,
                              void* d_out, int out_size)
{
    const float* x  = (const float*)d_in[0];
    const float* Wr = (const float*)d_in[1];
    const float* br = (const float*)d_in[2];
    const float* We = (const float*)d_in[3];
    float* out = (float*)d_out;
    (void)in_sizes; (void)n_in; (void)out_size;

    router_kernel<<<N_TOK / 8, 256>>>(x, Wr, br);
    hist_kernel<<<2 * NCHUNK, 256>>>();
    scan_kernel<<<1, N_EXP>>>();
    assign_kernel<<<2 * NCHUNK, 32>>>();
    dim3 gg(D_DIM / 128, (CAPACITY + 127) / 128, N_EXP);
    expert_gemm<<<gg, 256>>>(x, We);
    combine_kernel<<<N_TOK, 256>>>(out);
}

// round 4
// speedup vs baseline: 2.2579x; 2.2579x over previous
#include <cuda_runtime.h>
#include <cuda_bf16.h>
#include <math.h>
#include <stdint.h>

#define N_TOK 16384
#define D_DIM 1024
#define N_EXP 64
#define CAPACITY 640
#define CHUNK 256
#define NCHUNK (N_TOK / CHUNK)   // 64

#define KB 32                    // k per pipeline chunk
#define NCHUNKS_K (D_DIM / KB)   // 32

// ---------------- scratch (static device globals; no runtime alloc) ----------
__device__ int   g_topidx[N_TOK * 2];
__device__ float g_gates [N_TOK * 2];
__device__ int   g_hist  [2 * NCHUNK * N_EXP];
__device__ int   g_basep [2 * NCHUNK * N_EXP];
__device__ int   g_cnt   [N_EXP];
__device__ int   g_slot  [N_TOK * 2];
__device__ int   g_toklist[N_EXP * CAPACITY];
__device__ float g_ybuf[(size_t)N_TOK * 2 * D_DIM];

__device__ __nv_bfloat16 g_xhi[(size_t)N_TOK * D_DIM];
__device__ __nv_bfloat16 g_xlo[(size_t)N_TOK * D_DIM];
// B planes, K-major: B[e][n][k] = We[e][k][n]
__device__ __nv_bfloat16 g_Bhi[(size_t)N_EXP * D_DIM * D_DIM];
__device__ __nv_bfloat16 g_Blo[(size_t)N_EXP * D_DIM * D_DIM];

// ---------------- ptx helpers -------------------------------------------------
__device__ __forceinline__ uint32_t smem_u32(const void* p) {
    uint32_t a;
    asm("{ .reg .u64 t; cvta.to.shared.u64 t, %1; cvt.u32.u64 %0, t; }" : "=r"(a) : "l"(p));
    return a;
}
#define CP_ASYNC16(dst, src) \
    asm volatile("cp.async.cg.shared.global [%0], [%1], 16;" :: "r"(dst), "l"(src))
#define CP_COMMIT() asm volatile("cp.async.commit_group;" ::: "memory")
#define CP_WAIT1()  asm volatile("cp.async.wait_group 1;" ::: "memory")
#define CP_WAIT0()  asm volatile("cp.async.wait_group 0;" ::: "memory")

__device__ __forceinline__ void ldsm4(uint32_t* r, uint32_t addr) {
    asm volatile("ldmatrix.sync.aligned.m8n8.x4.shared.b16 {%0,%1,%2,%3}, [%4];"
        : "=r"(r[0]), "=r"(r[1]), "=r"(r[2]), "=r"(r[3]) : "r"(addr));
}
__device__ __forceinline__ void mma16816(float* d, const uint32_t* a,
                                         const uint32_t* b) {
    asm volatile("mma.sync.aligned.m16n8k16.row.col.f32.bf16.bf16.f32 "
        "{%0,%1,%2,%3}, {%4,%5,%6,%7}, {%8,%9}, {%0,%1,%2,%3};"
        : "+f"(d[0]), "+f"(d[1]), "+f"(d[2]), "+f"(d[3])
        : "r"(a[0]), "r"(a[1]), "r"(a[2]), "r"(a[3]), "r"(b[0]), "r"(b[1]));
}

// ---------------- conversions -------------------------------------------------
__global__ __launch_bounds__(256) void conv_x_kernel(const float* __restrict__ x)
{
    size_t i = ((size_t)blockIdx.x * 256 + threadIdx.x) * 4;
    float4 v = *(const float4*)(x + i);
    __nv_bfloat16 h0 = __float2bfloat16(v.x), h1 = __float2bfloat16(v.y);
    __nv_bfloat16 h2 = __float2bfloat16(v.z), h3 = __float2bfloat16(v.w);
    __nv_bfloat16 l0 = __float2bfloat16(v.x - __bfloat162float(h0));
    __nv_bfloat16 l1 = __float2bfloat16(v.y - __bfloat162float(h1));
    __nv_bfloat16 l2 = __float2bfloat16(v.z - __bfloat162float(h2));
    __nv_bfloat16 l3 = __float2bfloat16(v.w - __bfloat162float(h3));
    *(ushort4*)(g_xhi + i) = make_ushort4(*(uint16_t*)&h0, *(uint16_t*)&h1,
                                          *(uint16_t*)&h2, *(uint16_t*)&h3);
    *(ushort4*)(g_xlo + i) = make_ushort4(*(uint16_t*)&l0, *(uint16_t*)&l1,
                                          *(uint16_t*)&l2, *(uint16_t*)&l3);
}

// transpose + split: B[e][n][k] = We[e][k][n]
__global__ __launch_bounds__(256) void conv_We_kernel(const float* __restrict__ We)
{
    __shared__ float t[32][33];
    int e = blockIdx.z;
    int d0 = blockIdx.x * 32, h0 = blockIdx.y * 32;
    int tx = threadIdx.x, ty = threadIdx.y;   // (32, 8)
    const float* src = We + (size_t)e * D_DIM * D_DIM;
    #pragma unroll
    for (int i = 0; i < 4; ++i) {
        int r = ty + i * 8;
        t[r][tx] = src[(size_t)(d0 + r) * D_DIM + h0 + tx];
    }
    __syncthreads();
    #pragma unroll
    for (int i = 0; i < 4; ++i) {
        int r = ty + i * 8;
        float v = t[tx][r];
        __nv_bfloat16 hi = __float2bfloat16(v);
        __nv_bfloat16 lo = __float2bfloat16(v - __bfloat162float(hi));
        size_t off = ((size_t)e * D_DIM + h0 + r) * D_DIM + d0 + tx;
        g_Bhi[off] = hi;
        g_Blo[off] = lo;
    }
}

// ---------------- router ------------------------------------------------------
__device__ __forceinline__ bool beats(float v, int i, float v2, int i2) {
    return (v > v2) || (v == v2 && i < i2);
}

__global__ __launch_bounds__(256) void router_kernel(
    const float* __restrict__ x, const float* __restrict__ Wr,
    const float* __restrict__ br)
{
    __shared__ float WrS[64 * 64];
    __shared__ float xS[8 * 64];
    int tid  = threadIdx.x;
    int warp = tid >> 5, lane = tid & 31;
    int token = blockIdx.x * 8 + warp;
    const float* xrow = x + (size_t)token * D_DIM;

    int ea = 2 * lane, eb = 2 * lane + 1;
    float acc0 = br[ea], acc1 = br[eb];

    for (int d0 = 0; d0 < D_DIM; d0 += 64) {
        __syncthreads();
        for (int i = tid; i < 64 * 16; i += 256) {
            int r = i >> 4, c4 = (i & 15) * 4;
            *(float4*)(WrS + r * 64 + c4) =
                *(const float4*)(Wr + (size_t)(d0 + r) * N_EXP + c4);
        }
        xS[warp * 64 + lane]      = xrow[d0 + lane];
        xS[warp * 64 + lane + 32] = xrow[d0 + lane + 32];
        __syncthreads();
        #pragma unroll
        for (int d = 0; d < 64; ++d) {
            float xv = xS[warp * 64 + d];
            float2 w = *(const float2*)(WrS + d * 64 + ea);
            acc0 = fmaf(xv, w.x, acc0);
            acc1 = fmaf(xv, w.y, acc1);
        }
    }

    float v1, v2; int i1, i2;
    if (beats(acc1, eb, acc0, ea)) { v1 = acc1; i1 = eb; v2 = acc0; i2 = ea; }
    else                           { v1 = acc0; i1 = ea; v2 = acc1; i2 = eb; }

    #pragma unroll
    for (int off = 16; off >= 1; off >>= 1) {
        float ov1 = __shfl_xor_sync(0xffffffffu, v1, off);
        int   oi1 = __shfl_xor_sync(0xffffffffu, i1, off);
        float ov2 = __shfl_xor_sync(0xffffffffu, v2, off);
        int   oi2 = __shfl_xor_sync(0xffffffffu, i2, off);
        if (beats(ov1, oi1, v1, i1)) {
            if (beats(ov2, oi2, v1, i1)) { v2 = ov2; i2 = oi2; }
            else                         { v2 = v1;  i2 = i1;  }
            v1 = ov1; i1 = oi1;
        } else {
            if (beats(ov1, oi1, v2, i2)) { v2 = ov1; i2 = oi1; }
        }
    }

    if (lane == 0) {
        float e1 = expf(v2 - v1);
        float inv = 1.0f / (1.0f + e1);
        g_topidx[2 * token]     = i1;
        g_topidx[2 * token + 1] = i2;
        g_gates [2 * token]     = inv;
        g_gates [2 * token + 1] = e1 * inv;
    }
}

// ---------------- histogram / scan / assign -----------------------------------
__global__ __launch_bounds__(256) void hist_kernel()
{
    int k = blockIdx.x >> 6, chunk = blockIdx.x & 63;
    __shared__ int cnt[N_EXP];
    int tid = threadIdx.x;
    if (tid < N_EXP) cnt[tid] = 0;
    __syncthreads();
    int token = chunk * CHUNK + tid;
    int e = g_topidx[token * 2 + k];
    atomicAdd(&cnt[e], 1);
    __syncthreads();
    if (tid < N_EXP) g_hist[(k * NCHUNK + chunk) * N_EXP + tid] = cnt[tid];
}

__global__ void scan_kernel()
{
    int e = threadIdx.x;
    int run = 0;
    for (int i = 0; i < 2 * NCHUNK; ++i) {
        g_basep[i * N_EXP + e] = run;
        run += g_hist[i * N_EXP + e];
    }
    g_cnt[e] = run < CAPACITY ? run : CAPACITY;
}

__global__ __launch_bounds__(32) void assign_kernel()
{
    int k = blockIdx.x >> 6, chunk = blockIdx.x & 63;
    int lane = threadIdx.x;
    __shared__ int run[N_EXP];
    run[lane] = 0; run[lane + 32] = 0;
    __syncwarp();
    int baseoff = (k * NCHUNK + chunk) * N_EXP;
    #pragma unroll
    for (int g = 0; g < CHUNK / 32; ++g) {
        int token = chunk * CHUNK + g * 32 + lane;
        int e = g_topidx[token * 2 + k];
        unsigned m = __match_any_sync(0xffffffffu, e);
        int leader = __ffs(m) - 1;
        int rank = __popc(m & ((1u << lane) - 1u));
        int old = 0;
        if (lane == leader) old = atomicAdd(&run[e], __popc(m));
        old = __shfl_sync(0xffffffffu, old, leader);
        int slot = g_basep[baseoff + e] + old + rank;
        g_slot[token * 2 + k] = slot;
        if (slot < CAPACITY) g_toklist[e * CAPACITY + slot] = token * 2 + k;
    }
}

// ---------------- mma.sync grouped expert GEMM --------------------------------
// 128x128 tile, Kchunk=32, split-bf16 3-pass, 8 warps (4m x 2n), warp tile 32x64.
// SMEM per stage: A_hi, A_lo, B_hi, B_lo each [128 rows][32 k] bf16 with 80B
// row pitch (40 bf16) -> 10240B per plane, 40960B per stage, 2 stages = 80KB.
#define PITCH_B 80
#define PLANE_BYTES (128 * PITCH_B)       // 10240
#define STAGE_BYTES (4 * PLANE_BYTES)     // 40960
#define SMEM_GEMM   (2 * STAGE_BYTES)     // 81920

__global__ __launch_bounds__(256, 2) void expert_gemm_mma()
{
    extern __shared__ char smem[];
    __shared__ int rowent[128];
    __shared__ int tokrow[128];

    int e = blockIdx.z;
    int cnt = g_cnt[e];
    int m0 = blockIdx.y * 128;
    if (m0 >= cnt) return;
    int n0 = blockIdx.x * 128;

    int tid = threadIdx.x;
    int lane = tid & 31;
    int wm = (tid >> 5) & 3;       // warp m quadrant (rows wm*32..)
    int wn = tid >> 7;             // warp n half (cols wn*64..)
    uint32_t sbase = smem_u32(smem);

    if (tid < 128) {
        int r = m0 + tid;
        int ent = (r < cnt) ? g_toklist[e * CAPACITY + r] : -1;
        rowent[tid] = ent;
        tokrow[tid] = (ent >= 0) ? (ent >> 1) : 0;
    }
    __syncthreads();

    const size_t bexp = (size_t)e * D_DIM * D_DIM;

    // ---- async stage loader: 2048 x 16B (A: 1024, B: 1024) ----
    auto load_stage = [&](int stage, int c) {
        size_t koff = (size_t)c * KB;
        uint32_t sb = sbase + stage * STAGE_BYTES;
        #pragma unroll
        for (int j = 0; j < 8; ++j) {
            int idx = tid + j * 256;
            int isB = idx >> 10;
            int t = idx & 1023;
            int plane = t >> 9, u = t & 511, r = u >> 2, seg = u & 3;
            const __nv_bfloat16* src;
            if (!isB)
                src = (plane ? g_xlo : g_xhi)
                    + (size_t)tokrow[r] * D_DIM + koff + seg * 8;
            else
                src = (plane ? g_Blo : g_Bhi)
                    + bexp + (size_t)(n0 + r) * D_DIM + koff + seg * 8;
            uint32_t dst = sb + (isB ? 2 * PLANE_BYTES : 0)
                         + plane * PLANE_BYTES + r * PITCH_B + seg * 16;
            CP_ASYNC16(dst, src);
        }
    };

    // ldmatrix address components
    int a_row = wm * 32 + (lane & 15);
    int a_colb = (lane >> 4) * 16;                    // bytes (8 bf16)
    int b_row = wn * 64 + ((lane >> 4) & 1) * 8 + (lane & 7);
    int b_colb = ((lane >> 3) & 1) * 16;              // bytes

    float acc[2][8][4];
    #pragma unroll
    for (int mt = 0; mt < 2; ++mt)
        #pragma unroll
        for (int nf = 0; nf < 8; ++nf)
            #pragma unroll
            for (int q = 0; q < 4; ++q) acc[mt][nf][q] = 0.f;

    load_stage(0, 0);
    CP_COMMIT();

    const int pa[3] = {0, 0, 1};   // A plane per pass (0=hi,1=lo)
    const int pb[3] = {0, 1, 0};   // B plane per pass

    for (int c = 0; c < NCHUNKS_K; ++c) {
        if (c + 1 < NCHUNKS_K) {
            load_stage((c + 1) & 1, c + 1);
            CP_COMMIT();
            CP_WAIT1();
        } else {
            CP_WAIT0();
        }
        __syncthreads();

        uint32_t sb = sbase + (c & 1) * STAGE_BYTES;
        #pragma unroll
        for (int ks = 0; ks < 2; ++ks) {
            #pragma unroll
            for (int p = 0; p < 3; ++p) {
                uint32_t a0[4], a1[4];
                uint32_t abase = sb + pa[p] * PLANE_BYTES + a_colb + ks * 32;
                ldsm4(a0, abase + a_row * PITCH_B);
                ldsm4(a1, abase + (a_row + 16) * PITCH_B);
                uint32_t bb[4][4];
                uint32_t bbase = sb + 2 * PLANE_BYTES + pb[p] * PLANE_BYTES
                               + b_colb + ks * 32;
                #pragma unroll
                for (int nt = 0; nt < 4; ++nt)
                    ldsm4(bb[nt], bbase + (b_row + nt * 16) * PITCH_B);
                #pragma unroll
                for (int nt = 0; nt < 4; ++nt) {
                    mma16816(acc[0][2 * nt],     a0, &bb[nt][0]);
                    mma16816(acc[0][2 * nt + 1], a0, &bb[nt][2]);
                    mma16816(acc[1][2 * nt],     a1, &bb[nt][0]);
                    mma16816(acc[1][2 * nt + 1], a1, &bb[nt][2]);
                }
            }
        }
        __syncthreads();
    }

    // ---- epilogue: relu + scatter to g_ybuf ----
    int colb = (lane & 3) * 2;
    #pragma unroll
    for (int mt = 0; mt < 2; ++mt) {
        #pragma unroll
        for (int h = 0; h < 2; ++h) {
            int row = wm * 32 + mt * 16 + (lane >> 2) + h * 8;
            int ent = rowent[row];
            if (ent < 0) continue;
            float* yrow = g_ybuf + (size_t)ent * D_DIM + n0 + wn * 64 + colb;
            #pragma unroll
            for (int nf = 0; nf < 8; ++nf) {
                float2 o;
                o.x = fmaxf(acc[mt][nf][h * 2],     0.f);
                o.y = fmaxf(acc[mt][nf][h * 2 + 1], 0.f);
                *(float2*)(yrow + nf * 8) = o;
            }
        }
    }
}

// ---------------- combine -----------------------------------------------------
__global__ __launch_bounds__(256) void combine_kernel(float* __restrict__ out)
{
    int t = blockIdx.x;
    int d = threadIdx.x * 4;
    int s0 = g_slot[2 * t], s1 = g_slot[2 * t + 1];
    float g0 = g_gates[2 * t], g1 = g_gates[2 * t + 1];
    float4 acc = make_float4(0.f, 0.f, 0.f, 0.f);
    if (s0 < CAPACITY) {
        float4 v = *(const float4*)(g_ybuf + (size_t)(2 * t) * D_DIM + d);
        acc.x += g0 * v.x; acc.y += g0 * v.y; acc.z += g0 * v.z; acc.w += g0 * v.w;
    }
    if (s1 < CAPACITY) {
        float4 v = *(const float4*)(g_ybuf + (size_t)(2 * t + 1) * D_DIM + d);
        acc.x += g1 * v.x; acc.y += g1 * v.y; acc.z += g1 * v.z; acc.w += g1 * v.w;
    }
    *(float4*)(out + (size_t)t * D_DIM + d) = acc;
}

// ---------------- launch ------------------------------------------------------
extern "C" void kernel_launch(void* const* d_in, const int* in_sizes, int n_in,
                              void* d_out, int out_size)
{
    const float* x  = (const float*)d_in[0];
    const float* Wr = (const float*)d_in[1];
    const float* br = (const float*)d_in[2];
    const float* We = (const float*)d_in[3];
    float* out = (float*)d_out;
    (void)in_sizes; (void)n_in; (void)out_size;

    static bool attr_done = false;
    if (!attr_done) {
        cudaFuncSetAttribute(expert_gemm_mma,
                             cudaFuncAttributeMaxDynamicSharedMemorySize,
                             SMEM_GEMM);
        attr_done = true;
    }

    conv_x_kernel<<<(N_TOK * D_DIM) / (256 * 4), 256>>>(x);
    dim3 wg(32, 32, 64);
    conv_We_kernel<<<wg, dim3(32, 8)>>>(We);
    router_kernel<<<N_TOK / 8, 256>>>(x, Wr, br);
    hist_kernel<<<2 * NCHUNK, 256>>>();
    scan_kernel<<<1, N_EXP>>>();
    assign_kernel<<<2 * NCHUNK, 32>>>();
    dim3 gg(D_DIM / 128, (CAPACITY + 127) / 128, N_EXP);
    expert_gemm_mma<<<gg, 256, SMEM_GEMM>>>();
    combine_kernel<<<N_TOK, 256>>>(out);
}